// round 12
// baseline (speedup 1.0000x reference)
#include <cuda_runtime.h>
#include <math.h>
#include <stdint.h>

#define BZ    8
#define IM    128
#define HW    (IM * IM)        // 16384
#define CIN   3

#define NPROD       128        // 16 col-groups * 8 batches
#define PROD_PER_B  16
#define NCONS       (129 * BZ) // 1032

// E[b][o][w] = leakyrelu(W @ S);  handshake counters (self-resetting).
__device__ float g_E[BZ * IM * IM];
__device__ int   g_prod[BZ];
__device__ int   g_cons[BZ];

// __launch_bounds__(256, 8): cap regs at 32 so the 1032 store-only consumer
// blocks run at full (thread-limited) occupancy — the producer path spills a
// few epilogue registers instead, which is hidden under the store stream.
__global__ void __launch_bounds__(256, 8) fused_kernel(const float* __restrict__ x,
                                                       const float* __restrict__ conv_w,
                                                       float* __restrict__ out) {
    // ~13.3 KB static smem: 8 blocks/SM x 13.3 KB = 106 KB < 227 KB, so
    // occupancy stays thread-limited.
    __shared__ float  sRe[8][IM], sIm[8][IM];                     // 8 KB
    __shared__ float4 sST4[8 * 32];                               // 4 KB: S^T swizzled
    __shared__ float  t128c[IM], t128s[IM], t32c[32], t32s[32];   // 1.25 KB

    const int bid = blockIdx.x;
    const int tid = threadIdx.x;

    if (bid < NPROD) {
        // ============ PRODUCER: DFT (8 cols) + GEMM (128 o x 8 w) ============
        const int b    = bid >> 4;
        const int cg   = bid & 15;        // columns [cg*8, cg*8+8)
        const int wid  = tid >> 5;        // warp -> local column (0..7)
        const int lane = tid & 31;

        // Load 8 columns (both channels): 512 float4.
        const float* xb = x + (size_t)b * CIN * HW;
        for (int idx = tid; idx < 512; idx += 256) {
            int ch = idx >> 8, rem = idx & 255;
            int h = rem >> 1, half = rem & 1;
            float4 v = ((const float4*)(xb + (size_t)ch * HW))[h * (IM / 4) + 2 * cg + half];
            float (*dst)[IM] = ch ? sIm : sRe;
            dst[half * 4 + 0][h] = v.x; dst[half * 4 + 1][h] = v.y;
            dst[half * 4 + 2][h] = v.z; dst[half * 4 + 3][h] = v.w;
        }

        // Twiddle tables (exact).
        if (tid < 160) {
            float s, c;
            if (tid < 128) {
                sincosf(-6.283185307179586f * (float)tid * (1.0f / 128.0f), &s, &c);
                t128c[tid] = c; t128s[tid] = s;
            } else {
                int k = tid - 128;
                sincosf(-6.283185307179586f * (float)k * (1.0f / 32.0f), &s, &c);
                t32c[k] = c; t32s[k] = s;
            }
        }
        __syncthreads();

        // Radix-4 DFT: warp wid handles its column; lane -> outputs
        // lane, lane+32, lane+64, lane+96.
        float A0r = 0, A0i = 0, A1r = 0, A1i = 0, A2r = 0, A2i = 0, A3r = 0, A3i = 0;
        const float4* r4 = (const float4*)sRe[wid];
        const float4* m4 = (const float4*)sIm[wid];

#pragma unroll
        for (int t = 0; t < 32; t++) {
            int   k = (lane * t) & 31;
            float c = t32c[k], s = t32s[k];
            float4 xr = r4[t];
            float4 xm = m4[t];
            A0r = fmaf(xr.x, c, A0r); A0r = fmaf(-xm.x, s, A0r);
            A0i = fmaf(xr.x, s, A0i); A0i = fmaf( xm.x, c, A0i);
            A1r = fmaf(xr.y, c, A1r); A1r = fmaf(-xm.y, s, A1r);
            A1i = fmaf(xr.y, s, A1i); A1i = fmaf( xm.y, c, A1i);
            A2r = fmaf(xr.z, c, A2r); A2r = fmaf(-xm.z, s, A2r);
            A2i = fmaf(xr.z, s, A2i); A2i = fmaf( xm.z, c, A2i);
            A3r = fmaf(xr.w, c, A3r); A3r = fmaf(-xm.w, s, A3r);
            A3i = fmaf(xr.w, s, A3i); A3i = fmaf( xm.w, c, A3i);
        }

        float cw = t128c[lane],             sw = t128s[lane];
        float c2 = t128c[(2 * lane) & 127], s2 = t128s[(2 * lane) & 127];
        float c3 = t128c[(3 * lane) & 127], s3 = t128s[(3 * lane) & 127];

        float T0r = A0r,                 T0i = A0i;
        float T1r = cw * A1r - sw * A1i, T1i = cw * A1i + sw * A1r;
        float T2r = c2 * A2r - s2 * A2i, T2i = c2 * A2i + s2 * A2r;
        float T3r = c3 * A3r - s3 * A3i, T3i = c3 * A3i + s3 * A3r;

        float Er = T0r + T2r, Ei = T0i + T2i;
        float Fr = T1r + T3r, Fi = T1i + T3i;
        float Gr = T0r - T2r, Gi = T0i - T2i;
        float Hr = T1r - T3r, Hi = T1i - T3i;

        float m0r = Er + Fr, m0i = Ei + Fi;
        float m2r = Er - Fr, m2i = Ei - Fi;
        float m1r = Gr + Hi, m1i = Gi - Hr;
        float m3r = Gr - Hi, m3i = Gi + Hr;

        const float inv = 1.0f / 128.0f;
        float* sSTf = (float*)sST4;
        // Store S^T swizzled: float i of column wid -> float4-slot
        // (wid*32 + ((i>>2) ^ wid)), sub (i & 3). Conflict-free both phases.
        {
            float mv[4] = { sqrtf(m0r * m0r + m0i * m0i) * inv,
                            sqrtf(m1r * m1r + m1i * m1i) * inv,
                            sqrtf(m2r * m2r + m2i * m2i) * inv,
                            sqrtf(m3r * m3r + m3i * m3i) * inv };
#pragma unroll
            for (int q = 0; q < 4; q++) {
                int i = lane + 32 * q;
                sSTf[(wid * 32 + ((i >> 2) ^ wid)) * 4 + (i & 3)] = mv[q];
            }
        }
        __syncthreads();

        // GEMM: per pass, warp handles one o; lanes = (w in 0..7, ksub in 0..3).
        // W load is warp-uniform in w -> 4 distinct 16B addresses per LDG.
        const int wloc = lane & 7;
        const int ksub = lane >> 3;
        const float4* W4 = (const float4*)conv_w;

#pragma unroll 4
        for (int pass = 0; pass < 16; pass++) {
            int o = pass * 8 + wid;
            float acc = 0.0f;
#pragma unroll
            for (int j = 0; j < 8; j++) {
                int i4 = ksub * 8 + j;
                float4 wv = W4[o * 32 + i4];                 // L1-hot
                float4 sv = sST4[wloc * 32 + (i4 ^ wloc)];   // conflict-free
                acc = fmaf(wv.x, sv.x, acc); acc = fmaf(wv.y, sv.y, acc);
                acc = fmaf(wv.z, sv.z, acc); acc = fmaf(wv.w, sv.w, acc);
            }
            acc += __shfl_xor_sync(0xFFFFFFFF, acc, 8);
            acc += __shfl_xor_sync(0xFFFFFFFF, acc, 16);
            if (ksub == 0) {
                float e = (acc >= 0.0f) ? acc : 0.2f * acc;
                g_E[(size_t)(b * IM + o) * IM + cg * 8 + wloc] = e;
            }
        }

        // Publish: make E visible gpu-wide, then bump the batch counter.
        __threadfence();
        __syncthreads();
        if (tid == 0) atomicAdd(&g_prod[b], 1);

    } else {
        // ================= CONSUMER: broadcast one (b,o) row =================
        const int cid = bid - NPROD;
        const int b   = cid / 129;
        const int o   = cid - b * 129;

        if (o == IM) {
            // Independent passthrough of x channel 2 — no wait needed.
            float4*       d4  = (float4*)(out + (size_t)(b * (IM + 1) + IM) * HW);
            const float4* src = (const float4*)(x + (size_t)b * CIN * HW + 2 * HW);
#pragma unroll
            for (int j = tid; j < HW / 4; j += 256) d4[j] = src[j];
            return;
        }

        // Wait for batch b's producers (all blocks co-resident: 1160 <= 1184).
        if (tid == 0) {
            volatile int* p = g_prod + b;
            while (*p < PROD_PER_B) __nanosleep(64);
        }
        __syncthreads();
        __threadfence();                               // acquire ordering

        const float4* e4 = (const float4*)(g_E + (size_t)(b * IM + o) * IM);
        float4 v = __ldcg(e4 + (tid & 31));            // L2 read, skip L1
        float4* out4 = (float4*)(out + (size_t)(b * (IM + 1) + o) * HW);
        const int w4 = tid & 31;
        const int h0 = tid >> 5;                       // 0..7
#pragma unroll
        for (int h = h0; h < IM; h += 8) out4[h * (IM / 4) + w4] = v;

        // Reset protocol: 128th consumer of batch b zeroes both counters
        // (safe: every consumer increments only after its poll succeeded).
        __syncthreads();
        if (tid == 0) {
            int old = atomicAdd(&g_cons[b], 1);
            if (old == IM - 1) {
                *(volatile int*)&g_prod[b] = 0;
                *(volatile int*)&g_cons[b] = 0;
            }
        }
    }
}

// ---------------------------------------------------------------------------
extern "C" void kernel_launch(void* const* d_in, const int* in_sizes, int n_in,
                              void* d_out, int out_size) {
    const float* x      = (const float*)d_in[0];
    const float* conv_w = (const float*)d_in[2];
    float*       out    = (float*)d_out;

    fused_kernel<<<NPROD + NCONS, 256>>>(x, conv_w, out);
}

// round 13
// speedup vs baseline: 1.6278x; 1.6278x over previous
#include <cuda_runtime.h>
#include <math.h>
#include <stdint.h>

#define BZ    8
#define IM    128
#define HW    (IM * IM)        // 16384
#define CIN   3

// E[b][o][w] = leakyrelu(W @ S)
__device__ float g_E[BZ * IM * IM];

// ---------------------------------------------------------------------------
// K1: DFT with 4-warp t-split per column + warp-uniform GEMM.
// grid = (32 col-groups, 8 b), block = 512 threads = 16 warps.
// warp (col = wid>>2, q = wid&3): partial radix-4 DFT over t in [8q, 8q+8),
// combine partials in smem, warp q produces output quarter q, then GEMM.
// ---------------------------------------------------------------------------
__global__ void __launch_bounds__(512) dft_gemm_kernel(const float* __restrict__ x,
                                                       const float* __restrict__ conv_w) {
    __shared__ float  sRe[4][IM], sIm[4][IM];          // 4 KB
    __shared__ float  sP[4][4][8][32];                 // 16 KB partial accumulators
    __shared__ float4 sST4[4 * 32];                    // 2 KB: S^T swizzled
    __shared__ float  t128c[IM], t128s[IM], t32c[32], t32s[32];   // 1.25 KB

    const int cg   = blockIdx.x;      // columns [cg*4, cg*4+4)
    const int b    = blockIdx.y;
    const int tid  = threadIdx.x;
    const int wid  = tid >> 5;        // 0..15
    const int lane = tid & 31;
    const int col  = wid >> 2;        // local column 0..3
    const int q    = wid & 3;         // t-quarter 0..3

    // Load 4 columns (both channels): 256 float4 (threads 0..255).
    if (tid < 256) {
        int ch = tid >> 7, h = tid & 127;
        const float* xb = x + (size_t)b * CIN * HW + (size_t)ch * HW;
        float4 v = ((const float4*)xb)[h * (IM / 4) + cg];
        float (*dst)[IM] = ch ? sIm : sRe;
        dst[0][h] = v.x; dst[1][h] = v.y; dst[2][h] = v.z; dst[3][h] = v.w;
    }

    // Twiddle tables (exact).
    if (tid < 160) {
        float s, c;
        if (tid < 128) {
            sincosf(-6.283185307179586f * (float)tid * (1.0f / 128.0f), &s, &c);
            t128c[tid] = c; t128s[tid] = s;
        } else {
            int k = tid - 128;
            sincosf(-6.283185307179586f * (float)k * (1.0f / 32.0f), &s, &c);
            t32c[k] = c; t32s[k] = s;
        }
    }
    __syncthreads();

    // Partial radix-4 DFT: 8 t-steps, 16 FMA each.
    float A0r = 0, A0i = 0, A1r = 0, A1i = 0, A2r = 0, A2i = 0, A3r = 0, A3i = 0;
    const float4* r4 = (const float4*)sRe[col];
    const float4* m4 = (const float4*)sIm[col];

#pragma unroll
    for (int tt = 0; tt < 8; tt++) {
        int   t = q * 8 + tt;
        int   k = (lane * t) & 31;
        float c = t32c[k], s = t32s[k];
        float4 xr = r4[t];      // samples 4t..4t+3, broadcast across warp
        float4 xm = m4[t];
        A0r = fmaf(xr.x, c, A0r); A0r = fmaf(-xm.x, s, A0r);
        A0i = fmaf(xr.x, s, A0i); A0i = fmaf( xm.x, c, A0i);
        A1r = fmaf(xr.y, c, A1r); A1r = fmaf(-xm.y, s, A1r);
        A1i = fmaf(xr.y, s, A1i); A1i = fmaf( xm.y, c, A1i);
        A2r = fmaf(xr.z, c, A2r); A2r = fmaf(-xm.z, s, A2r);
        A2i = fmaf(xr.z, s, A2i); A2i = fmaf( xm.z, c, A2i);
        A3r = fmaf(xr.w, c, A3r); A3r = fmaf(-xm.w, s, A3r);
        A3i = fmaf(xr.w, s, A3i); A3i = fmaf( xm.w, c, A3i);
    }

    // Publish partials (lane-major: conflict-free).
    sP[col][q][0][lane] = A0r; sP[col][q][1][lane] = A0i;
    sP[col][q][2][lane] = A1r; sP[col][q][3][lane] = A1i;
    sP[col][q][4][lane] = A2r; sP[col][q][5][lane] = A2i;
    sP[col][q][6][lane] = A3r; sP[col][q][7][lane] = A3i;
    __syncthreads();

    // Combine: warp (col, q) produces output quarter q of its column.
    {
        float a[8];
#pragma unroll
        for (int v = 0; v < 8; v++)
            a[v] = sP[col][0][v][lane] + sP[col][1][v][lane]
                 + sP[col][2][v][lane] + sP[col][3][v][lane];

        float cw = t128c[lane],             sw = t128s[lane];
        float c2 = t128c[(2 * lane) & 127], s2 = t128s[(2 * lane) & 127];
        float c3 = t128c[(3 * lane) & 127], s3 = t128s[(3 * lane) & 127];

        float T0r = a[0],                T0i = a[1];
        float T1r = cw * a[2] - sw * a[3], T1i = cw * a[3] + sw * a[2];
        float T2r = c2 * a[4] - s2 * a[5], T2i = c2 * a[5] + s2 * a[4];
        float T3r = c3 * a[6] - s3 * a[7], T3i = c3 * a[7] + s3 * a[6];

        float Er = T0r + T2r, Ei = T0i + T2i;
        float Fr = T1r + T3r, Fi = T1i + T3i;
        float Gr = T0r - T2r, Gi = T0i - T2i;
        float Hr = T1r - T3r, Hi = T1i - T3i;

        float mr, mi;                              // warp-uniform select on q
        if      (q == 0) { mr = Er + Fr; mi = Ei + Fi; }
        else if (q == 1) { mr = Gr + Hi; mi = Gi - Hr; }
        else if (q == 2) { mr = Er - Fr; mi = Ei - Fi; }
        else             { mr = Gr - Hi; mi = Gi + Hr; }

        float mag = sqrtf(mr * mr + mi * mi) * (1.0f / 128.0f);
        int   i   = lane + 32 * q;
        // S^T swizzled store: float i of column col -> float4-slot
        // (col*32 + ((i>>2) ^ col)), sub (i & 3). Conflict-free.
        ((float*)sST4)[(col * 32 + ((i >> 2) ^ col)) * 4 + (i & 3)] = mag;
    }
    __syncthreads();

    // GEMM: 8 passes; warp handles o = pass*16 + wid.
    // lanes = (wloc in 0..3 [w-column], ksub in 0..7 [k-split]).
    const int wloc = lane & 3;
    const int ksub = lane >> 2;
    const float4* W4 = (const float4*)conv_w;

#pragma unroll
    for (int pass = 0; pass < 8; pass++) {
        int o = pass * 16 + wid;
        float acc = 0.0f;
#pragma unroll
        for (int j = 0; j < 4; j++) {
            int i4 = ksub * 4 + j;
            float4 wv = W4[o * 32 + i4];                   // L1-hot, 8 addrs/warp
            float4 sv = sST4[wloc * 32 + (i4 ^ wloc)];     // conflict-free
            acc = fmaf(wv.x, sv.x, acc); acc = fmaf(wv.y, sv.y, acc);
            acc = fmaf(wv.z, sv.z, acc); acc = fmaf(wv.w, sv.w, acc);
        }
        acc += __shfl_xor_sync(0xFFFFFFFF, acc, 4);
        acc += __shfl_xor_sync(0xFFFFFFFF, acc, 8);
        acc += __shfl_xor_sync(0xFFFFFFFF, acc, 16);
        if (ksub == 0) {
            float e = (acc >= 0.0f) ? acc : 0.2f * acc;
            g_E[(size_t)(b * IM + o) * IM + cg * 4 + wloc] = e;
        }
    }
}

// ---------------------------------------------------------------------------
// K2: broadcast E over h into out; o==128 copies x channel 2. (R5-proven.)
// grid = (129 o, 8 b), block = 256 threads.
// ---------------------------------------------------------------------------
__global__ void __launch_bounds__(256) bcast_kernel(const float* __restrict__ x,
                                                    float* __restrict__ out) {
    const int o   = blockIdx.x;    // 0..128
    const int b   = blockIdx.y;
    const int tid = threadIdx.x;

    float4* out4 = (float4*)(out + (size_t)(b * (IM + 1) + o) * HW);

    if (o == IM) {
        const float4* src = (const float4*)(x + (size_t)b * CIN * HW + 2 * HW);
#pragma unroll
        for (int j = tid; j < HW / 4; j += 256) out4[j] = src[j];
        return;
    }

    const float4* e4 = (const float4*)(g_E + (size_t)(b * IM + o) * IM);
    float4 v = e4[tid & 31];           // register-resident row chunk
    const int w4 = tid & 31;
    const int h0 = tid >> 5;           // 0..7
#pragma unroll
    for (int h = h0; h < IM; h += 8) out4[h * (IM / 4) + w4] = v;
}

// ---------------------------------------------------------------------------
extern "C" void kernel_launch(void* const* d_in, const int* in_sizes, int n_in,
                              void* d_out, int out_size) {
    const float* x      = (const float*)d_in[0];
    const float* conv_w = (const float*)d_in[2];
    float*       out    = (float*)d_out;

    dft_gemm_kernel<<<dim3(32, BZ), 512>>>(x, conv_w);
    bcast_kernel<<<dim3(IM + 1, BZ), 256>>>(x, out);
}